// round 1
// baseline (speedup 1.0000x reference)
#include <cuda_runtime.h>
#include <math.h>

#define T_LEN 2048
#define S_LEN 2048
#define BATCH 2
#define EMB   1024
#define HEADS 16
#define DHEAD 64
#define MROWS (T_LEN*BATCH)      // 4096
#define SCALING 0.125f
#define D_THRESH 3.8918202981106265f

// ---------------- scratch (device globals: the sanctioned no-alloc workaround) ----
__device__ __align__(16) float g_q[(size_t)MROWS*EMB];
__device__ __align__(16) float g_k[(size_t)MROWS*EMB];
__device__ __align__(16) float g_v[(size_t)MROWS*EMB];
__device__ __align__(16) float g_attn[(size_t)MROWS*EMB];
// fallback weights buffer, only used if d_out doesn't include attn_weights
__device__ __align__(16) float g_w[(size_t)BATCH*HEADS*T_LEN*S_LEN];

// ============================================================================
// GEMM: C[M,N] = alpha * (A[M,K] @ W[N,K]^T + bias[N])   (all row-major)
// BM=BN=128, BK=16, 256 threads, 8x8 microtile (split-64 col/row mapping)
// ============================================================================
__global__ __launch_bounds__(256, 2)
void proj_gemm(const float* __restrict__ A, const float* __restrict__ W,
               const float* __restrict__ bias, float* __restrict__ C,
               int M, int N, int K, float alpha)
{
    __shared__ __align__(16) float As[16*132];
    __shared__ __align__(16) float Bs[16*132];

    const int tid = threadIdx.x;
    const int tx = tid & 15, ty = tid >> 4;
    const int tx4 = tx*4, ty4 = ty*4;
    const int m0 = blockIdx.y * 128, n0 = blockIdx.x * 128;

    float acc[8][8];
    #pragma unroll
    for (int i = 0; i < 8; i++)
        #pragma unroll
        for (int j = 0; j < 8; j++) acc[i][j] = 0.f;

    for (int k0 = 0; k0 < K; k0 += 16) {
        __syncthreads();
        #pragma unroll
        for (int i = 0; i < 2; i++) {
            int u = tid + 256*i;
            int r  = u >> 2;
            int kq = (u & 3) * 4;
            float4 va = *(const float4*)&A[(size_t)(m0 + r)*K + k0 + kq];
            As[(kq+0)*132 + r] = va.x;
            As[(kq+1)*132 + r] = va.y;
            As[(kq+2)*132 + r] = va.z;
            As[(kq+3)*132 + r] = va.w;
            float4 vb = *(const float4*)&W[(size_t)(n0 + r)*K + k0 + kq];
            Bs[(kq+0)*132 + r] = vb.x;
            Bs[(kq+1)*132 + r] = vb.y;
            Bs[(kq+2)*132 + r] = vb.z;
            Bs[(kq+3)*132 + r] = vb.w;
        }
        __syncthreads();
        #pragma unroll
        for (int kk = 0; kk < 16; kk++) {
            float4 a0 = *(const float4*)&As[kk*132 + ty4];
            float4 a1 = *(const float4*)&As[kk*132 + 64 + ty4];
            float4 b0 = *(const float4*)&Bs[kk*132 + tx4];
            float4 b1 = *(const float4*)&Bs[kk*132 + 64 + tx4];
            float av[8] = {a0.x,a0.y,a0.z,a0.w, a1.x,a1.y,a1.z,a1.w};
            float bv[8] = {b0.x,b0.y,b0.z,b0.w, b1.x,b1.y,b1.z,b1.w};
            #pragma unroll
            for (int i = 0; i < 8; i++)
                #pragma unroll
                for (int j = 0; j < 8; j++)
                    acc[i][j] += av[i]*bv[j];
        }
    }

    float bb[8];
    #pragma unroll
    for (int j = 0; j < 4; j++) {
        bb[j]   = bias[n0 + tx4 + j];
        bb[4+j] = bias[n0 + 64 + tx4 + j];
    }
    #pragma unroll
    for (int i = 0; i < 8; i++) {
        int row = m0 + ((i < 4) ? (ty4 + i) : (64 + ty4 + i - 4));
        float4 o0, o1;
        o0.x = alpha*(acc[i][0] + bb[0]); o0.y = alpha*(acc[i][1] + bb[1]);
        o0.z = alpha*(acc[i][2] + bb[2]); o0.w = alpha*(acc[i][3] + bb[3]);
        o1.x = alpha*(acc[i][4] + bb[4]); o1.y = alpha*(acc[i][5] + bb[5]);
        o1.z = alpha*(acc[i][6] + bb[6]); o1.w = alpha*(acc[i][7] + bb[7]);
        *(float4*)&C[(size_t)row*N + n0 + tx4]      = o0;
        *(float4*)&C[(size_t)row*N + n0 + 64 + tx4] = o1;
    }
}

// ============================================================================
// Fused scores + mask + dynamic-threshold + softmax.
// grid = (T/16, B*H), 256 threads.  smem: ws[16][2048] | kt[128][65] | qs[16][65]
// Writes normalized attn_weights [z, t, s] to wout.
// ============================================================================
#define SMEM_B_FLOATS (16*2048 + 128*65 + 16*65)

__global__ __launch_bounds__(256, 1)
void attn_softmax(const float* __restrict__ gq, const float* __restrict__ gk,
                  const int* __restrict__ mask, float* __restrict__ wout)
{
    extern __shared__ float sm[];
    float* ws = sm;                      // 16 x 2048
    float* kt = sm + 16*2048;            // 128 x 65
    float* qs = kt + 128*65;             // 16 x 65

    const int tid = threadIdx.x;
    const int z = blockIdx.y;
    const int b = z / HEADS, h = z % HEADS;
    const int t0 = blockIdx.x * 16;

    // load 16 q rows (already scaled in projection)
    for (int u = tid; u < 16*64; u += 256) {
        int r = u >> 6, d = u & 63;
        qs[r*65 + d] = gq[((size_t)(t0 + r)*BATCH + b)*EMB + h*64 + d];
    }

    const int tt = tid >> 6;     // 0..3  (4 t-rows each)
    const int ss = tid & 63;     // 0..63 (2 s each: ss, ss+64)

    for (int st = 0; st < 16; st++) {
        const int s0 = st * 128;
        __syncthreads();
        for (int u = tid; u < 128*64; u += 256) {
            int r = u >> 6, d = u & 63;
            kt[r*65 + d] = gk[((size_t)(s0 + r)*BATCH + b)*EMB + h*64 + d];
        }
        __syncthreads();

        float acc[4][2];
        #pragma unroll
        for (int i = 0; i < 4; i++) { acc[i][0] = 0.f; acc[i][1] = 0.f; }

        #pragma unroll 8
        for (int d = 0; d < 64; d++) {
            float b0 = kt[ss*65 + d];
            float b1 = kt[(ss + 64)*65 + d];
            #pragma unroll
            for (int i = 0; i < 4; i++) {
                float a = qs[(tt*4 + i)*65 + d];
                acc[i][0] += a * b0;
                acc[i][1] += a * b1;
            }
        }
        #pragma unroll
        for (int i = 0; i < 4; i++) {
            ws[(tt*4 + i)*2048 + s0 + ss]      = acc[i][0];
            ws[(tt*4 + i)*2048 + s0 + ss + 64] = acc[i][1];
        }
    }
    __syncthreads();

    // softmax: 8 warps, 2 rows per warp
    const int w = tid >> 5, lane = tid & 31;
    for (int rr = 0; rr < 2; rr++) {
        const int r = w*2 + rr;
        const int t = t0 + r;
        float m = -INFINITY;
        for (int k2 = 0; k2 < 64; k2++) {
            int sidx = k2*32 + lane;
            float v = ws[r*2048 + sidx];
            if (mask[(size_t)t*S_LEN + sidx] == 0) v = -INFINITY;
            ws[r*2048 + sidx] = v;
            m = fmaxf(m, v);
        }
        #pragma unroll
        for (int o = 16; o > 0; o >>= 1) m = fmaxf(m, __shfl_xor_sync(0xffffffffu, m, o));
        const float thr = m - D_THRESH;
        float sum = 0.f;
        for (int k2 = 0; k2 < 64; k2++) {
            int sidx = k2*32 + lane;
            float v = ws[r*2048 + sidx];
            float p = (v >= thr) ? __expf(v - m) : 0.f;
            ws[r*2048 + sidx] = p;
            sum += p;
        }
        #pragma unroll
        for (int o = 16; o > 0; o >>= 1) sum += __shfl_xor_sync(0xffffffffu, sum, o);
        const float inv = 1.f / sum;
        const size_t base = ((size_t)z*T_LEN + t)*S_LEN;
        for (int k2 = 0; k2 < 64; k2++) {
            int sidx = k2*32 + lane;
            wout[base + sidx] = ws[r*2048 + sidx] * inv;
        }
    }
}

// ============================================================================
// attn = weights @ V  (per z: [2048,2048] x [2048,64])
// grid = (T/128, B*H), 256 threads. Thread: 8 t x 4 dv.
// Writes g_attn in (t*B+b, h*64+dv) layout for the output GEMM.
// ============================================================================
__global__ __launch_bounds__(256, 3)
void attn_v(const float* __restrict__ wgt, const float* __restrict__ gv,
            float* __restrict__ out)
{
    __shared__ __align__(16) float ws2[128*33];
    __shared__ __align__(16) float vs[32*68];

    const int tid = threadIdx.x;
    const int z = blockIdx.y;
    const int b = z / HEADS, h = z % HEADS;
    const int t0 = blockIdx.x * 128;
    const int tg = tid >> 4;        // 0..15 -> rows tg*8..tg*8+7
    const int vg = tid & 15;        // 0..15 -> dv = vg*4..vg*4+3
    const int vg4 = vg * 4;

    float acc[8][4];
    #pragma unroll
    for (int i = 0; i < 8; i++)
        #pragma unroll
        for (int j = 0; j < 4; j++) acc[i][j] = 0.f;

    for (int s0 = 0; s0 < S_LEN; s0 += 32) {
        __syncthreads();
        #pragma unroll
        for (int i = 0; i < 4; i++) {
            int u4 = tid + 256*i;
            int r  = u4 >> 3;
            int c4 = (u4 & 7) * 4;
            float4 t4 = *(const float4*)&wgt[((size_t)z*T_LEN + t0 + r)*S_LEN + s0 + c4];
            ws2[r*33 + c4 + 0] = t4.x;
            ws2[r*33 + c4 + 1] = t4.y;
            ws2[r*33 + c4 + 2] = t4.z;
            ws2[r*33 + c4 + 3] = t4.w;
        }
        #pragma unroll
        for (int i = 0; i < 2; i++) {
            int u4 = tid + 256*i;
            int r  = u4 >> 4;
            int c4 = (u4 & 15) * 4;
            *(float4*)&vs[r*68 + c4] =
                *(const float4*)&gv[((size_t)(s0 + r)*BATCH + b)*EMB + h*64 + c4];
        }
        __syncthreads();

        #pragma unroll 8
        for (int s = 0; s < 32; s++) {
            float4 bv4 = *(const float4*)&vs[s*68 + vg4];
            #pragma unroll
            for (int i = 0; i < 8; i++) {
                float a = ws2[(tg*8 + i)*33 + s];
                acc[i][0] += a * bv4.x;
                acc[i][1] += a * bv4.y;
                acc[i][2] += a * bv4.z;
                acc[i][3] += a * bv4.w;
            }
        }
    }

    #pragma unroll
    for (int i = 0; i < 8; i++) {
        int t = t0 + tg*8 + i;
        float4 o;
        o.x = acc[i][0]; o.y = acc[i][1]; o.z = acc[i][2]; o.w = acc[i][3];
        *(float4*)&out[((size_t)t*BATCH + b)*EMB + h*64 + vg4] = o;
    }
}

// ============================================================================
extern "C" void kernel_launch(void* const* d_in, const int* in_sizes, int n_in,
                              void* d_out, int out_size)
{
    const float* query = (const float*)d_in[0];
    const float* key   = (const float*)d_in[1];
    const float* value = (const float*)d_in[2];
    const int*   mask  = (const int*)  d_in[3];
    const float* Wq = (const float*)d_in[4];  const float* bq = (const float*)d_in[5];
    const float* Wk = (const float*)d_in[6];  const float* bk = (const float*)d_in[7];
    const float* Wv = (const float*)d_in[8];  const float* bv = (const float*)d_in[9];
    const float* Wo = (const float*)d_in[10]; const float* bo = (const float*)d_in[11];
    float* out = (float*)d_out;

    float *gq, *gk, *gv, *ga, *gw;
    cudaGetSymbolAddress((void**)&gq, g_q);
    cudaGetSymbolAddress((void**)&gk, g_k);
    cudaGetSymbolAddress((void**)&gv, g_v);
    cudaGetSymbolAddress((void**)&ga, g_attn);
    cudaGetSymbolAddress((void**)&gw, g_w);

    const size_t attn_elems = (size_t)T_LEN*BATCH*EMB;             // 4,194,304
    const size_t w_elems    = (size_t)BATCH*HEADS*T_LEN*S_LEN;     // 134,217,728
    float* wptr = ((size_t)out_size >= attn_elems + w_elems) ? (out + attn_elems) : gw;

    static const int smem_b = SMEM_B_FLOATS * (int)sizeof(float);  // ~164.6 KB
    cudaFuncSetAttribute(attn_softmax, cudaFuncAttributeMaxDynamicSharedMemorySize, smem_b);

    dim3 gemm_grid(EMB/128, MROWS/128);   // (8, 32)

    // input projections (scaling folded into Q)
    proj_gemm<<<gemm_grid, 256>>>(query, Wq, bq, gq, MROWS, EMB, EMB, SCALING);
    proj_gemm<<<gemm_grid, 256>>>(key,   Wk, bk, gk, MROWS, EMB, EMB, 1.0f);
    proj_gemm<<<gemm_grid, 256>>>(value, Wv, bv, gv, MROWS, EMB, EMB, 1.0f);

    // fused scores + mask + threshold + softmax -> attn_weights
    attn_softmax<<<dim3(T_LEN/16, BATCH*HEADS), 256, smem_b>>>(gq, gk, mask, wptr);

    // attn = weights @ V
    attn_v<<<dim3(T_LEN/128, BATCH*HEADS), 256>>>(wptr, gv, ga);

    // output projection -> attn output (first out_size segment)
    proj_gemm<<<gemm_grid, 256>>>(ga, Wo, bo, out, MROWS, EMB, EMB, 1.0f);
}

// round 5
// speedup vs baseline: 1.0493x; 1.0493x over previous
#include <cuda_runtime.h>
#include <cuda_bf16.h>
#include <math.h>
#include <stdint.h>

#define T_LEN 2048
#define S_LEN 2048
#define BATCH 2
#define EMB   1024
#define HEADS 16
#define MROWS (T_LEN*BATCH)      // 4096
#define SCALING 0.125f
#define D_THRESH 3.8918202981106265f

// ---------------- scratch (device globals) ----------------
__device__ __align__(16) float g_q[(size_t)MROWS*EMB];
__device__ __align__(16) float g_k[(size_t)MROWS*EMB];
__device__ __align__(16) float g_v[(size_t)MROWS*EMB];
__device__ __align__(16) float g_attn[(size_t)MROWS*EMB];
__device__ __align__(16) float g_w[(size_t)BATCH*HEADS*T_LEN*S_LEN];
// bf16 split planes (reused across sequential GEMMs)
__device__ __align__(16) __nv_bfloat16 g_ah[(size_t)MROWS*EMB];
__device__ __align__(16) __nv_bfloat16 g_al[(size_t)MROWS*EMB];
__device__ __align__(16) __nv_bfloat16 g_wh[(size_t)EMB*EMB];
__device__ __align__(16) __nv_bfloat16 g_wl[(size_t)EMB*EMB];

// ======================= helpers =======================
static __device__ __forceinline__ uint32_t s2u(const void* p) {
    uint32_t a;
    asm("{ .reg .u64 t; cvta.to.shared.u64 t, %1; cvt.u32.u64 %0, t; }" : "=r"(a) : "l"(p));
    return a;
}
static __device__ __forceinline__ void cpa16(uint32_t dst, const void* src) {
    asm volatile("cp.async.cg.shared.global [%0], [%1], 16;" :: "r"(dst), "l"(src) : "memory");
}
static __device__ __forceinline__ void ldsm4(uint32_t* r, uint32_t addr) {
    asm volatile("ldmatrix.sync.aligned.m8n8.x4.shared.b16 {%0,%1,%2,%3}, [%4];"
                 : "=r"(r[0]), "=r"(r[1]), "=r"(r[2]), "=r"(r[3]) : "r"(addr));
}
static __device__ __forceinline__ void mma_bf16(float* c, const uint32_t* a,
                                                uint32_t b0, uint32_t b1) {
    asm volatile("mma.sync.aligned.m16n8k16.row.col.f32.bf16.bf16.f32 "
                 "{%0,%1,%2,%3}, {%4,%5,%6,%7}, {%8,%9}, {%0,%1,%2,%3};"
                 : "+f"(c[0]), "+f"(c[1]), "+f"(c[2]), "+f"(c[3])
                 : "r"(a[0]), "r"(a[1]), "r"(a[2]), "r"(a[3]), "r"(b0), "r"(b1));
}

// ============================================================================
// fp32 -> bf16 hi/lo split (x = hi + lo, hi = rn(x), lo = rn(x - hi))
// ============================================================================
__global__ __launch_bounds__(256)
void split_f32(const float* __restrict__ x, __nv_bfloat16* __restrict__ hi,
               __nv_bfloat16* __restrict__ lo, int n4)
{
    int i = blockIdx.x * blockDim.x + threadIdx.x;
    int stride = gridDim.x * blockDim.x;
    for (; i < n4; i += stride) {
        float4 v = ((const float4*)x)[i];
        __nv_bfloat16 h0 = __float2bfloat16(v.x), h1 = __float2bfloat16(v.y);
        __nv_bfloat16 h2 = __float2bfloat16(v.z), h3 = __float2bfloat16(v.w);
        __nv_bfloat16 l0 = __float2bfloat16(v.x - __bfloat162float(h0));
        __nv_bfloat16 l1 = __float2bfloat16(v.y - __bfloat162float(h1));
        __nv_bfloat16 l2 = __float2bfloat16(v.z - __bfloat162float(h2));
        __nv_bfloat16 l3 = __float2bfloat16(v.w - __bfloat162float(h3));
        ((__nv_bfloat162*)hi)[i*2]   = __halves2bfloat162(h0, h1);
        ((__nv_bfloat162*)hi)[i*2+1] = __halves2bfloat162(h2, h3);
        ((__nv_bfloat162*)lo)[i*2]   = __halves2bfloat162(l0, l1);
        ((__nv_bfloat162*)lo)[i*2+1] = __halves2bfloat162(l2, l3);
    }
}

// ============================================================================
// HMMA bf16 3-split GEMM: C[m][n] = alpha * (sum_k A[m,k]*W[n,k] + bias[n])
// M=4096, N=1024, K=1024. CTA tile 128x128, K-chunks of 32, double-buffered
// cp.async. 8 warps as 4(M)x2(N): warp tile 32x64. m16n8k16 fragments.
// smem plane: 128 rows x 32 bf16 cols at stride 40 elems (80 B).
// ============================================================================
#define GK 1024
#define GN 1024
#define NCHUNK 32
#define PL_STRIDE 40
#define PL_ELEMS (128*PL_STRIDE)          // 5120 elems
#define BUF_ELEMS (4*PL_ELEMS)            // 20480 elems
#define GEMM_DSMEM (2*BUF_ELEMS*2)        // 81920 bytes

__global__ __launch_bounds__(256)
void gemm_mma_bf16x3(const __nv_bfloat16* __restrict__ Ahi, const __nv_bfloat16* __restrict__ Alo,
                     const __nv_bfloat16* __restrict__ Bhi, const __nv_bfloat16* __restrict__ Blo,
                     const float* __restrict__ bias, float* __restrict__ C, float alpha)
{
    extern __shared__ __align__(16) __nv_bfloat16 smb[];
    const uint32_t sbase = s2u(smb);

    const int tid = threadIdx.x;
    const int lane = tid & 31, wid = tid >> 5;
    const int wm = wid & 3, wn = wid >> 2;          // 4 x 2 warp grid
    const int m0 = blockIdx.y * 128, n0 = blockIdx.x * 128;

    const __nv_bfloat16* gsrc[4] = {Ahi, Alo, Bhi, Blo};
    const int rowb[4] = {m0, m0, n0, n0};

    float acc[2][8][4];
    #pragma unroll
    for (int mf = 0; mf < 2; mf++)
        #pragma unroll
        for (int nf = 0; nf < 8; nf++)
            #pragma unroll
            for (int q = 0; q < 4; q++) acc[mf][nf][q] = 0.f;

    // per-thread cp.async (dst, row, col) pairs: 4 planes x 2 chunks
    const int ld_r = tid >> 2;                 // 0..63 (x2 via +64)... actually 512 chunks/plane
    // 512 chunks per plane: u = tid + 256*i, r = u>>2 (0..127), c16 = u&3
    // ldmatrix per-lane geometry
    const int rowA = lane & 15;
    const int kA   = (lane >> 4) << 3;
    const int rowB = ((lane >> 4) << 3) + (lane & 7);
    const int kB   = ((lane >> 3) & 1) << 3;
    (void)ld_r;

    #define ISSUE_LOAD(cidx, buf) do {                                                 \
        const int _k0 = (cidx) * 32;                                                   \
        _Pragma("unroll")                                                              \
        for (int p = 0; p < 4; p++) {                                                  \
            const __nv_bfloat16* S = gsrc[p];                                          \
            const int rb = rowb[p];                                                    \
            _Pragma("unroll")                                                          \
            for (int i = 0; i < 2; i++) {                                              \
                int u = tid + 256*i;                                                   \
                int r = u >> 2, c16 = u & 3;                                           \
                uint32_t dst = sbase + (uint32_t)(((buf)*BUF_ELEMS + p*PL_ELEMS +      \
                                         r*PL_STRIDE + c16*8) * 2);                    \
                cpa16(dst, &S[(size_t)(rb + r)*GK + _k0 + c16*8]);                     \
            }                                                                          \
        }                                                                              \
        asm volatile("cp.async.commit_group;" ::: "memory");                           \
    } while (0)

    ISSUE_LOAD(0, 0);

    for (int c = 0; c < NCHUNK; c++) {
        const int buf = c & 1;
        if (c + 1 < NCHUNK) {
            ISSUE_LOAD(c + 1, buf ^ 1);
            asm volatile("cp.async.wait_group 1;" ::: "memory");
        } else {
            asm volatile("cp.async.wait_group 0;" ::: "memory");
        }
        __syncthreads();

        const uint32_t bofs = sbase + (uint32_t)(buf * BUF_ELEMS * 2);
        const uint32_t aplaneH = bofs;
        const uint32_t aplaneL = bofs + PL_ELEMS*2;
        const uint32_t bplaneH = bofs + 2*PL_ELEMS*2;
        const uint32_t bplaneL = bofs + 3*PL_ELEMS*2;

        #pragma unroll
        for (int ks = 0; ks < 2; ks++) {
            const int k16 = ks * 16;
            uint32_t ah[2][4], al[2][4];
            #pragma unroll
            for (int mf = 0; mf < 2; mf++) {
                uint32_t off = (uint32_t)(((wm*32 + mf*16 + rowA)*PL_STRIDE + k16 + kA) * 2);
                ldsm4(ah[mf], aplaneH + off);
                ldsm4(al[mf], aplaneL + off);
            }
            #pragma unroll
            for (int ng = 0; ng < 4; ng++) {
                uint32_t bh[4], bl[4];
                uint32_t off = (uint32_t)(((wn*64 + ng*16 + rowB)*PL_STRIDE + k16 + kB) * 2);
                ldsm4(bh, bplaneH + off);
                ldsm4(bl, bplaneL + off);
                #pragma unroll
                for (int mf = 0; mf < 2; mf++) {
                    #pragma unroll
                    for (int nf2 = 0; nf2 < 2; nf2++) {
                        float* a4 = acc[mf][ng*2 + nf2];
                        mma_bf16(a4, ah[mf], bh[2*nf2], bh[2*nf2+1]);
                        mma_bf16(a4, ah[mf], bl[2*nf2], bl[2*nf2+1]);
                        mma_bf16(a4, al[mf], bh[2*nf2], bh[2*nf2+1]);
                    }
                }
            }
        }
        __syncthreads();
    }

    // epilogue: c0,c1 -> (row, col..col+1); c2,c3 -> (row+8, ...)
    const int tq = lane >> 2, tr = lane & 3;
    #pragma unroll
    for (int mf = 0; mf < 2; mf++) {
        #pragma unroll
        for (int nf = 0; nf < 8; nf++) {
            const int row = m0 + wm*32 + mf*16 + tq;
            const int col = n0 + wn*64 + nf*8 + tr*2;
            const float b0 = __ldg(&bias[col]), b1 = __ldg(&bias[col+1]);
            float2 o0, o1;
            o0.x = alpha*(acc[mf][nf][0] + b0); o0.y = alpha*(acc[mf][nf][1] + b1);
            o1.x = alpha*(acc[mf][nf][2] + b0); o1.y = alpha*(acc[mf][nf][3] + b1);
            *(float2*)&C[(size_t)row*GN + col]       = o0;
            *(float2*)&C[(size_t)(row+8)*GN + col]   = o1;
        }
    }
}

// ============================================================================
// Fused scores + mask + dynamic-threshold + softmax
// ============================================================================
#define SMEM_B_FLOATS (16*2048 + 128*65 + 16*65)

__global__ __launch_bounds__(256, 1)
void attn_softmax(const float* __restrict__ gq, const float* __restrict__ gk,
                  const int* __restrict__ mask, float* __restrict__ wout)
{
    extern __shared__ float sm[];
    float* ws = sm;                      // 16 x 2048
    float* kt = sm + 16*2048;            // 128 x 65
    float* qs = kt + 128*65;             // 16 x 65

    const int tid = threadIdx.x;
    const int z = blockIdx.y;
    const int b = z / HEADS, h = z % HEADS;
    const int t0 = blockIdx.x * 16;

    for (int u = tid; u < 16*64; u += 256) {
        int r = u >> 6, d = u & 63;
        qs[r*65 + d] = gq[((size_t)(t0 + r)*BATCH + b)*EMB + h*64 + d];
    }

    const int tt = tid >> 6;
    const int ss = tid & 63;

    for (int st = 0; st < 16; st++) {
        const int s0 = st * 128;
        __syncthreads();
        for (int u = tid; u < 128*64; u += 256) {
            int r = u >> 6, d = u & 63;
            kt[r*65 + d] = gk[((size_t)(s0 + r)*BATCH + b)*EMB + h*64 + d];
        }
        __syncthreads();

        float acc[4][2];
        #pragma unroll
        for (int i = 0; i < 4; i++) { acc[i][0] = 0.f; acc[i][1] = 0.f; }

        #pragma unroll 8
        for (int d = 0; d < 64; d++) {
            float b0 = kt[ss*65 + d];
            float b1 = kt[(ss + 64)*65 + d];
            #pragma unroll
            for (int i = 0; i < 4; i++) {
                float a = qs[(tt*4 + i)*65 + d];
                acc[i][0] += a * b0;
                acc[i][1] += a * b1;
            }
        }
        #pragma unroll
        for (int i = 0; i < 4; i++) {
            ws[(tt*4 + i)*2048 + s0 + ss]      = acc[i][0];
            ws[(tt*4 + i)*2048 + s0 + ss + 64] = acc[i][1];
        }
    }
    __syncthreads();

    const int w = tid >> 5, lane = tid & 31;
    for (int rr = 0; rr < 2; rr++) {
        const int r = w*2 + rr;
        const int t = t0 + r;
        float m = -INFINITY;
        for (int k2 = 0; k2 < 64; k2++) {
            int sidx = k2*32 + lane;
            float v = ws[r*2048 + sidx];
            if (mask[(size_t)t*S_LEN + sidx] == 0) v = -INFINITY;
            ws[r*2048 + sidx] = v;
            m = fmaxf(m, v);
        }
        #pragma unroll
        for (int o = 16; o > 0; o >>= 1) m = fmaxf(m, __shfl_xor_sync(0xffffffffu, m, o));
        const float thr = m - D_THRESH;
        float sum = 0.f;
        for (int k2 = 0; k2 < 64; k2++) {
            int sidx = k2*32 + lane;
            float v = ws[r*2048 + sidx];
            float p = (v >= thr) ? __expf(v - m) : 0.f;
            ws[r*2048 + sidx] = p;
            sum += p;
        }
        #pragma unroll
        for (int o = 16; o > 0; o >>= 1) sum += __shfl_xor_sync(0xffffffffu, sum, o);
        const float inv = 1.f / sum;
        const size_t base = ((size_t)z*T_LEN + t)*S_LEN;
        for (int k2 = 0; k2 < 64; k2++) {
            int sidx = k2*32 + lane;
            wout[base + sidx] = ws[r*2048 + sidx] * inv;
        }
    }
}

// ============================================================================
// attn = weights @ V
// ============================================================================
__global__ __launch_bounds__(256, 3)
void attn_v(const float* __restrict__ wgt, const float* __restrict__ gv,
            float* __restrict__ out)
{
    __shared__ __align__(16) float ws2[128*33];
    __shared__ __align__(16) float vs[32*68];

    const int tid = threadIdx.x;
    const int z = blockIdx.y;
    const int b = z / HEADS, h = z % HEADS;
    const int t0 = blockIdx.x * 128;
    const int tg = tid >> 4;
    const int vg = tid & 15;
    const int vg4 = vg * 4;

    float acc[8][4];
    #pragma unroll
    for (int i = 0; i < 8; i++)
        #pragma unroll
        for (int j = 0; j < 4; j++) acc[i][j] = 0.f;

    for (int s0 = 0; s0 < S_LEN; s0 += 32) {
        __syncthreads();
        #pragma unroll
        for (int i = 0; i < 4; i++) {
            int u4 = tid + 256*i;
            int r  = u4 >> 3;
            int c4 = (u4 & 7) * 4;
            float4 t4 = *(const float4*)&wgt[((size_t)z*T_LEN + t0 + r)*S_LEN + s0 + c4];
            ws2[r*33 + c4 + 0] = t4.x;
            ws2[r*33 + c4 + 1] = t4.y;
            ws2[r*33 + c4 + 2] = t4.z;
            ws2[r*33 + c4 + 3] = t4.w;
        }
        #pragma unroll
        for (int i = 0; i < 2; i++) {
            int u4 = tid + 256*i;
            int r  = u4 >> 4;
            int c4 = (u4 & 15) * 4;
            *(float4*)&vs[r*68 + c4] =
                *(const float4*)&gv[((size_t)(s0 + r)*BATCH + b)*EMB + h*64 + c4];
        }
        __syncthreads();

        #pragma unroll 8
        for (int s = 0; s < 32; s++) {
            float4 bv4 = *(const float4*)&vs[s*68 + vg4];
            #pragma unroll
            for (int i = 0; i < 8; i++) {
                float a = ws2[(tg*8 + i)*33 + s];
                acc[i][0] += a * bv4.x;
                acc[i][1] += a * bv4.y;
                acc[i][2] += a * bv4.z;
                acc[i][3] += a * bv4.w;
            }
        }
    }

    #pragma unroll
    for (int i = 0; i < 8; i++) {
        int t = t0 + tg*8 + i;
        float4 o;
        o.x = acc[i][0]; o.y = acc[i][1]; o.z = acc[i][2]; o.w = acc[i][3];
        *(float4*)&out[((size_t)t*BATCH + b)*EMB + h*64 + vg4] = o;
    }
}

// ============================================================================
extern "C" void kernel_launch(void* const* d_in, const int* in_sizes, int n_in,
                              void* d_out, int out_size)
{
    const float* query = (const float*)d_in[0];
    const float* key   = (const float*)d_in[1];
    const float* value = (const float*)d_in[2];
    const int*   mask  = (const int*)  d_in[3];
    const float* Wq = (const float*)d_in[4];  const float* bq = (const float*)d_in[5];
    const float* Wk = (const float*)d_in[6];  const float* bk = (const float*)d_in[7];
    const float* Wv = (const float*)d_in[8];  const float* bv = (const float*)d_in[9];
    const float* Wo = (const float*)d_in[10]; const float* bo = (const float*)d_in[11];
    float* out = (float*)d_out;

    float *gq, *gk, *gv, *ga, *gw;
    __nv_bfloat16 *ah, *al, *wh, *wl;
    cudaGetSymbolAddress((void**)&gq, g_q);
    cudaGetSymbolAddress((void**)&gk, g_k);
    cudaGetSymbolAddress((void**)&gv, g_v);
    cudaGetSymbolAddress((void**)&ga, g_attn);
    cudaGetSymbolAddress((void**)&gw, g_w);
    cudaGetSymbolAddress((void**)&ah, g_ah);
    cudaGetSymbolAddress((void**)&al, g_al);
    cudaGetSymbolAddress((void**)&wh, g_wh);
    cudaGetSymbolAddress((void**)&wl, g_wl);

    const size_t attn_elems = (size_t)T_LEN*BATCH*EMB;             // 4,194,304
    const size_t w_elems    = (size_t)BATCH*HEADS*T_LEN*S_LEN;     // 134,217,728
    float* wptr = ((size_t)out_size >= attn_elems + w_elems) ? (out + attn_elems) : gw;

    static const int smem_sm = SMEM_B_FLOATS * (int)sizeof(float);
    cudaFuncSetAttribute(attn_softmax, cudaFuncAttributeMaxDynamicSharedMemorySize, smem_sm);
    cudaFuncSetAttribute(gemm_mma_bf16x3, cudaFuncAttributeMaxDynamicSharedMemorySize, GEMM_DSMEM);

    const int act_n4 = (MROWS*EMB)/4;   // 1,048,576
    const int w_n4   = (EMB*EMB)/4;     // 262,144
    dim3 gemm_grid(GN/128, MROWS/128);  // (8, 32)

    // Q projection (scaling folded)
    split_f32<<<1024, 256>>>(query, ah, al, act_n4);
    split_f32<<<512, 256>>>(Wq, wh, wl, w_n4);
    gemm_mma_bf16x3<<<gemm_grid, 256, GEMM_DSMEM>>>(ah, al, wh, wl, bq, gq, SCALING);

    // K projection
    split_f32<<<1024, 256>>>(key, ah, al, act_n4);
    split_f32<<<512, 256>>>(Wk, wh, wl, w_n4);
    gemm_mma_bf16x3<<<gemm_grid, 256, GEMM_DSMEM>>>(ah, al, wh, wl, bk, gk, 1.0f);

    // V projection
    split_f32<<<1024, 256>>>(value, ah, al, act_n4);
    split_f32<<<512, 256>>>(Wv, wh, wl, w_n4);
    gemm_mma_bf16x3<<<gemm_grid, 256, GEMM_DSMEM>>>(ah, al, wh, wl, bv, gv, 1.0f);

    // fused scores + mask + threshold + softmax -> attn_weights
    attn_softmax<<<dim3(T_LEN/16, BATCH*HEADS), 256, smem_sm>>>(gq, gk, mask, wptr);

    // attn = weights @ V
    attn_v<<<dim3(T_LEN/128, BATCH*HEADS), 256>>>(wptr, gv, ga);

    // output projection
    split_f32<<<1024, 256>>>(ga, ah, al, act_n4);
    split_f32<<<512, 256>>>(Wo, wh, wl, w_n4);
    gemm_mma_bf16x3<<<gemm_grid, 256, GEMM_DSMEM>>>(ah, al, wh, wl, bo, out, 1.0f);
}

// round 10
// speedup vs baseline: 2.5766x; 2.4556x over previous
#include <cuda_runtime.h>
#include <cuda_bf16.h>
#include <math.h>
#include <stdint.h>

#define T_LEN 2048
#define S_LEN 2048
#define BATCH 2
#define EMB   1024
#define HEADS 16
#define MROWS (T_LEN*BATCH)      // 4096
#define SCALING 0.125f
#define D_THRESH 3.8918202981106265f

// ---------------- scratch (device globals) ----------------
__device__ __align__(16) float g_q[(size_t)MROWS*EMB];
__device__ __align__(16) float g_k[(size_t)MROWS*EMB];
__device__ __align__(16) float g_v[(size_t)MROWS*EMB];
__device__ __align__(16) float g_attn[(size_t)MROWS*EMB];
__device__ __align__(16) float g_w[(size_t)BATCH*HEADS*T_LEN*S_LEN];
// bf16 split planes for GEMM inputs (reused across sequential GEMMs)
__device__ __align__(16) __nv_bfloat16 g_ah[(size_t)MROWS*EMB];
__device__ __align__(16) __nv_bfloat16 g_al[(size_t)MROWS*EMB];
__device__ __align__(16) __nv_bfloat16 g_wh[(size_t)EMB*EMB];
__device__ __align__(16) __nv_bfloat16 g_wl[(size_t)EMB*EMB];
// dedicated q/k split planes, and transposed v planes [z][dv][s]
__device__ __align__(16) __nv_bfloat16 g_qh[(size_t)MROWS*EMB];
__device__ __align__(16) __nv_bfloat16 g_ql[(size_t)MROWS*EMB];
__device__ __align__(16) __nv_bfloat16 g_kh[(size_t)MROWS*EMB];
__device__ __align__(16) __nv_bfloat16 g_kl[(size_t)MROWS*EMB];
__device__ __align__(16) __nv_bfloat16 g_vth[(size_t)MROWS*EMB];
__device__ __align__(16) __nv_bfloat16 g_vtl[(size_t)MROWS*EMB];

// ======================= helpers =======================
static __device__ __forceinline__ uint32_t s2u(const void* p) {
    uint32_t a;
    asm("{ .reg .u64 t; cvta.to.shared.u64 t, %1; cvt.u32.u64 %0, t; }" : "=r"(a) : "l"(p));
    return a;
}
static __device__ __forceinline__ void cpa16(uint32_t dst, const void* src) {
    asm volatile("cp.async.cg.shared.global [%0], [%1], 16;" :: "r"(dst), "l"(src) : "memory");
}
static __device__ __forceinline__ void ldsm4(uint32_t* r, uint32_t addr) {
    asm volatile("ldmatrix.sync.aligned.m8n8.x4.shared.b16 {%0,%1,%2,%3}, [%4];"
                 : "=r"(r[0]), "=r"(r[1]), "=r"(r[2]), "=r"(r[3]) : "r"(addr));
}
static __device__ __forceinline__ void mma_bf16(float* c, const uint32_t* a,
                                                uint32_t b0, uint32_t b1) {
    asm volatile("mma.sync.aligned.m16n8k16.row.col.f32.bf16.bf16.f32 "
                 "{%0,%1,%2,%3}, {%4,%5,%6,%7}, {%8,%9}, {%0,%1,%2,%3};"
                 : "+f"(c[0]), "+f"(c[1]), "+f"(c[2]), "+f"(c[3])
                 : "r"(a[0]), "r"(a[1]), "r"(a[2]), "r"(a[3]), "r"(b0), "r"(b1));
}
static __device__ __forceinline__ uint32_t pack_bf2(float a, float b) {
    return (uint32_t)__bfloat16_as_ushort(__float2bfloat16(a)) |
           ((uint32_t)__bfloat16_as_ushort(__float2bfloat16(b)) << 16);
}

// ============================================================================
// fp32 -> bf16 hi/lo split
// ============================================================================
__global__ __launch_bounds__(256)
void split_f32(const float* __restrict__ x, __nv_bfloat16* __restrict__ hi,
               __nv_bfloat16* __restrict__ lo, int n4)
{
    int i = blockIdx.x * blockDim.x + threadIdx.x;
    int stride = gridDim.x * blockDim.x;
    for (; i < n4; i += stride) {
        float4 v = ((const float4*)x)[i];
        __nv_bfloat16 h0 = __float2bfloat16(v.x), h1 = __float2bfloat16(v.y);
        __nv_bfloat16 h2 = __float2bfloat16(v.z), h3 = __float2bfloat16(v.w);
        __nv_bfloat16 l0 = __float2bfloat16(v.x - __bfloat162float(h0));
        __nv_bfloat16 l1 = __float2bfloat16(v.y - __bfloat162float(h1));
        __nv_bfloat16 l2 = __float2bfloat16(v.z - __bfloat162float(h2));
        __nv_bfloat16 l3 = __float2bfloat16(v.w - __bfloat162float(h3));
        ((__nv_bfloat162*)hi)[i*2]   = __halves2bfloat162(h0, h1);
        ((__nv_bfloat162*)hi)[i*2+1] = __halves2bfloat162(h2, h3);
        ((__nv_bfloat162*)lo)[i*2]   = __halves2bfloat162(l0, l1);
        ((__nv_bfloat162*)lo)[i*2+1] = __halves2bfloat162(l2, l3);
    }
}

// ============================================================================
// V transpose + split: g_v[(s*B+b)*EMB + h*64+dv] -> vt[hi/lo][z][dv][s]
// grid (S/128, B*H), 256 threads
// ============================================================================
__global__ __launch_bounds__(256)
void split_v_t(const float* __restrict__ gv, __nv_bfloat16* __restrict__ vth,
               __nv_bfloat16* __restrict__ vtl)
{
    __shared__ __align__(16) float tile[128*65];
    const int tid = threadIdx.x;
    const int z = blockIdx.y;
    const int b = z / HEADS, h = z % HEADS;
    const int s0 = blockIdx.x * 128;

    #pragma unroll
    for (int i = 0; i < 8; i++) {
        int u = tid + 256*i;          // 2048 float4 chunks
        int r = u >> 4, c4 = (u & 15) * 4;
        float4 v = *(const float4*)&gv[((size_t)(s0 + r)*BATCH + b)*EMB + h*64 + c4];
        tile[r*65 + c4 + 0] = v.x; tile[r*65 + c4 + 1] = v.y;
        tile[r*65 + c4 + 2] = v.z; tile[r*65 + c4 + 3] = v.w;
    }
    __syncthreads();

    const int dv = tid >> 2;
    const int sj = (tid & 3) * 32;
    uint32_t hbuf[16], lbuf[16];
    #pragma unroll
    for (int j = 0; j < 16; j++) {
        float x0 = tile[(sj + 2*j)*65 + dv];
        float x1 = tile[(sj + 2*j + 1)*65 + dv];
        __nv_bfloat16 h0 = __float2bfloat16(x0), h1 = __float2bfloat16(x1);
        hbuf[j] = (uint32_t)__bfloat16_as_ushort(h0) | ((uint32_t)__bfloat16_as_ushort(h1) << 16);
        lbuf[j] = pack_bf2(x0 - __bfloat162float(h0), x1 - __bfloat162float(h1));
    }
    const size_t base = ((size_t)z*64 + dv)*2048 + s0 + sj;
    #pragma unroll
    for (int q = 0; q < 4; q++) {
        *(uint4*)&vth[base + q*8] = *(uint4*)&hbuf[q*4];
        *(uint4*)&vtl[base + q*8] = *(uint4*)&lbuf[q*4];
    }
}

// ============================================================================
// HMMA bf16 3-split GEMM (unchanged from R5)
// ============================================================================
#define GK 1024
#define GN 1024
#define NCHUNK 32
#define PL_STRIDE 40
#define PL_ELEMS (128*PL_STRIDE)
#define BUF_ELEMS (4*PL_ELEMS)
#define GEMM_DSMEM (2*BUF_ELEMS*2)

__global__ __launch_bounds__(256)
void gemm_mma_bf16x3(const __nv_bfloat16* __restrict__ Ahi, const __nv_bfloat16* __restrict__ Alo,
                     const __nv_bfloat16* __restrict__ Bhi, const __nv_bfloat16* __restrict__ Blo,
                     const float* __restrict__ bias, float* __restrict__ C, float alpha)
{
    extern __shared__ __align__(16) __nv_bfloat16 smb[];
    const uint32_t sbase = s2u(smb);

    const int tid = threadIdx.x;
    const int lane = tid & 31, wid = tid >> 5;
    const int wm = wid & 3, wn = wid >> 2;
    const int m0 = blockIdx.y * 128, n0 = blockIdx.x * 128;

    const __nv_bfloat16* gsrc[4] = {Ahi, Alo, Bhi, Blo};
    const int rowb[4] = {m0, m0, n0, n0};

    float acc[2][8][4];
    #pragma unroll
    for (int mf = 0; mf < 2; mf++)
        #pragma unroll
        for (int nf = 0; nf < 8; nf++)
            #pragma unroll
            for (int q = 0; q < 4; q++) acc[mf][nf][q] = 0.f;

    const int rowA = lane & 15;
    const int kA   = (lane >> 4) << 3;
    const int rowB = ((lane >> 4) << 3) + (lane & 7);
    const int kB   = ((lane >> 3) & 1) << 3;

    #define ISSUE_LOAD(cidx, buf) do {                                                 \
        const int _k0 = (cidx) * 32;                                                   \
        _Pragma("unroll")                                                              \
        for (int p = 0; p < 4; p++) {                                                  \
            const __nv_bfloat16* S = gsrc[p];                                          \
            const int rb = rowb[p];                                                    \
            _Pragma("unroll")                                                          \
            for (int i = 0; i < 2; i++) {                                              \
                int u = tid + 256*i;                                                   \
                int r = u >> 2, c16 = u & 3;                                           \
                uint32_t dst = sbase + (uint32_t)(((buf)*BUF_ELEMS + p*PL_ELEMS +      \
                                         r*PL_STRIDE + c16*8) * 2);                    \
                cpa16(dst, &S[(size_t)(rb + r)*GK + _k0 + c16*8]);                     \
            }                                                                          \
        }                                                                              \
        asm volatile("cp.async.commit_group;" ::: "memory");                           \
    } while (0)

    ISSUE_LOAD(0, 0);

    for (int c = 0; c < NCHUNK; c++) {
        const int buf = c & 1;
        if (c + 1 < NCHUNK) {
            ISSUE_LOAD(c + 1, buf ^ 1);
            asm volatile("cp.async.wait_group 1;" ::: "memory");
        } else {
            asm volatile("cp.async.wait_group 0;" ::: "memory");
        }
        __syncthreads();

        const uint32_t bofs = sbase + (uint32_t)(buf * BUF_ELEMS * 2);
        const uint32_t aplaneH = bofs;
        const uint32_t aplaneL = bofs + PL_ELEMS*2;
        const uint32_t bplaneH = bofs + 2*PL_ELEMS*2;
        const uint32_t bplaneL = bofs + 3*PL_ELEMS*2;

        #pragma unroll
        for (int ks = 0; ks < 2; ks++) {
            const int k16 = ks * 16;
            uint32_t ah[2][4], al[2][4];
            #pragma unroll
            for (int mf = 0; mf < 2; mf++) {
                uint32_t off = (uint32_t)(((wm*32 + mf*16 + rowA)*PL_STRIDE + k16 + kA) * 2);
                ldsm4(ah[mf], aplaneH + off);
                ldsm4(al[mf], aplaneL + off);
            }
            #pragma unroll
            for (int ng = 0; ng < 4; ng++) {
                uint32_t bh[4], bl[4];
                uint32_t off = (uint32_t)(((wn*64 + ng*16 + rowB)*PL_STRIDE + k16 + kB) * 2);
                ldsm4(bh, bplaneH + off);
                ldsm4(bl, bplaneL + off);
                #pragma unroll
                for (int mf = 0; mf < 2; mf++) {
                    #pragma unroll
                    for (int nf2 = 0; nf2 < 2; nf2++) {
                        float* a4 = acc[mf][ng*2 + nf2];
                        mma_bf16(a4, ah[mf], bh[2*nf2], bh[2*nf2+1]);
                        mma_bf16(a4, ah[mf], bl[2*nf2], bl[2*nf2+1]);
                        mma_bf16(a4, al[mf], bh[2*nf2], bh[2*nf2+1]);
                    }
                }
            }
        }
        __syncthreads();
    }

    const int tq = lane >> 2, tr = lane & 3;
    #pragma unroll
    for (int mf = 0; mf < 2; mf++) {
        #pragma unroll
        for (int nf = 0; nf < 8; nf++) {
            const int row = m0 + wm*32 + mf*16 + tq;
            const int col = n0 + wn*64 + nf*8 + tr*2;
            const float b0 = __ldg(&bias[col]), b1 = __ldg(&bias[col+1]);
            float2 o0, o1;
            o0.x = alpha*(acc[mf][nf][0] + b0); o0.y = alpha*(acc[mf][nf][1] + b1);
            o1.x = alpha*(acc[mf][nf][2] + b0); o1.y = alpha*(acc[mf][nf][3] + b1);
            *(float2*)&C[(size_t)row*GN + col]       = o0;
            *(float2*)&C[(size_t)(row+8)*GN + col]   = o1;
        }
    }
}

// ============================================================================
// HMMA scores: raw S = Q Kt per z, tile 128t x 128s, K=64 single-shot.
// grid (S/128, T/128, B*H), 256 threads. smem 4 planes 128x64 @ stride 72.
// ============================================================================
#define QK_STR 72
#define QK_PLANE (128*QK_STR)             // 9216 elems
#define QK_DSMEM (4*QK_PLANE*2)           // 73728 bytes

__global__ __launch_bounds__(256)
void attn_qk(const __nv_bfloat16* __restrict__ qh, const __nv_bfloat16* __restrict__ ql,
             const __nv_bfloat16* __restrict__ kh, const __nv_bfloat16* __restrict__ kl,
             float* __restrict__ wout)
{
    extern __shared__ __align__(16) __nv_bfloat16 smq[];
    const uint32_t sbase = s2u(smq);

    const int tid = threadIdx.x;
    const int lane = tid & 31, wid = tid >> 5;
    const int wm = wid & 3, wn = wid >> 2;
    const int z = blockIdx.z;
    const int b = z / HEADS, h = z % HEADS;
    const int t0 = blockIdx.y * 128, s0 = blockIdx.x * 128;

    const __nv_bfloat16* gsrc[4] = {qh, ql, kh, kl};
    const int rowb[4] = {t0, t0, s0, s0};

    #pragma unroll
    for (int p = 0; p < 4; p++) {
        const __nv_bfloat16* S = gsrc[p];
        const int rb = rowb[p];
        #pragma unroll
        for (int i = 0; i < 4; i++) {
            int u = tid + 256*i;           // 1024 chunks per plane
            int r = u >> 3, c = u & 7;
            uint32_t dst = sbase + (uint32_t)((p*QK_PLANE + r*QK_STR + c*8) * 2);
            cpa16(dst, &S[((size_t)(rb + r)*BATCH + b)*EMB + h*64 + c*8]);
        }
    }
    asm volatile("cp.async.commit_group;" ::: "memory");
    asm volatile("cp.async.wait_group 0;" ::: "memory");
    __syncthreads();

    float acc[2][8][4];
    #pragma unroll
    for (int mf = 0; mf < 2; mf++)
        #pragma unroll
        for (int nf = 0; nf < 8; nf++)
            #pragma unroll
            for (int q = 0; q < 4; q++) acc[mf][nf][q] = 0.f;

    const int rowA = lane & 15;
    const int kA   = (lane >> 4) << 3;
    const int rowB = ((lane >> 4) << 3) + (lane & 7);
    const int kB   = ((lane >> 3) & 1) << 3;

    const uint32_t qH = sbase;
    const uint32_t qL = sbase + QK_PLANE*2;
    const uint32_t kH = sbase + 2*QK_PLANE*2;
    const uint32_t kL = sbase + 3*QK_PLANE*2;

    #pragma unroll
    for (int ks = 0; ks < 4; ks++) {
        const int k16 = ks * 16;
        uint32_t ah[2][4], al[2][4];
        #pragma unroll
        for (int mf = 0; mf < 2; mf++) {
            uint32_t off = (uint32_t)(((wm*32 + mf*16 + rowA)*QK_STR + k16 + kA) * 2);
            ldsm4(ah[mf], qH + off);
            ldsm4(al[mf], qL + off);
        }
        #pragma unroll
        for (int ng = 0; ng < 4; ng++) {
            uint32_t bh[4], bl[4];
            uint32_t off = (uint32_t)(((wn*64 + ng*16 + rowB)*QK_STR + k16 + kB) * 2);
            ldsm4(bh, kH + off);
            ldsm4(bl, kL + off);
            #pragma unroll
            for (int mf = 0; mf < 2; mf++) {
                #pragma unroll
                for (int nf2 = 0; nf2 < 2; nf2++) {
                    float* a4 = acc[mf][ng*2 + nf2];
                    mma_bf16(a4, ah[mf], bh[2*nf2], bh[2*nf2+1]);
                    mma_bf16(a4, ah[mf], bl[2*nf2], bl[2*nf2+1]);
                    mma_bf16(a4, al[mf], bh[2*nf2], bh[2*nf2+1]);
                }
            }
        }
    }

    const int tq = lane >> 2, tr = lane & 3;
    #pragma unroll
    for (int mf = 0; mf < 2; mf++) {
        #pragma unroll
        for (int nf = 0; nf < 8; nf++) {
            const int row = t0 + wm*32 + mf*16 + tq;
            const int col = s0 + wn*64 + nf*8 + tr*2;
            float2 o0, o1;
            o0.x = acc[mf][nf][0]; o0.y = acc[mf][nf][1];
            o1.x = acc[mf][nf][2]; o1.y = acc[mf][nf][3];
            *(float2*)&wout[((size_t)z*T_LEN + row)*S_LEN + col]     = o0;
            *(float2*)&wout[((size_t)z*T_LEN + row + 8)*S_LEN + col] = o1;
        }
    }
}

// ============================================================================
// Softmax pass: mask + dynamic threshold + softmax, in-place on wout.
// grid (T/16, B*H), 256 threads, smem 16x2048 fp32.
// ============================================================================
#define SM2_DSMEM (16*2048*4)

__global__ __launch_bounds__(256)
void attn_softmax2(float* __restrict__ wout, const int* __restrict__ mask)
{
    extern __shared__ float ws[];
    const int tid = threadIdx.x;
    const int z = blockIdx.y;
    const int t0 = blockIdx.x * 16;
    const size_t zbase = (size_t)z*T_LEN*S_LEN;

    #pragma unroll
    for (int i = 0; i < 32; i++) {
        int u = tid + 256*i;              // 8192 float4 chunks
        int r = u >> 9, c4 = (u & 511) * 4;
        *(float4*)&ws[r*2048 + c4] = *(const float4*)&wout[zbase + (size_t)(t0 + r)*S_LEN + c4];
    }
    __syncthreads();

    const int w = tid >> 5, lane = tid & 31;
    #pragma unroll
    for (int rr = 0; rr < 2; rr++) {
        const int r = w*2 + rr;
        const int t = t0 + r;
        float m = -INFINITY;
        for (int k2 = 0; k2 < 64; k2++) {
            int sidx = k2*32 + lane;
            float v = ws[r*2048 + sidx];
            if (mask[(size_t)t*S_LEN + sidx] == 0) v = -INFINITY;
            ws[r*2048 + sidx] = v;
            m = fmaxf(m, v);
        }
        #pragma unroll
        for (int o = 16; o > 0; o >>= 1) m = fmaxf(m, __shfl_xor_sync(0xffffffffu, m, o));
        const float thr = m - D_THRESH;
        float sum = 0.f;
        for (int k2 = 0; k2 < 64; k2++) {
            int sidx = k2*32 + lane;
            float v = ws[r*2048 + sidx];
            float p = (v >= thr) ? __expf(v - m) : 0.f;
            ws[r*2048 + sidx] = p;
            sum += p;
        }
        #pragma unroll
        for (int o = 16; o > 0; o >>= 1) sum += __shfl_xor_sync(0xffffffffu, sum, o);
        const float inv = 1.f / sum;
        const size_t base = zbase + (size_t)t*S_LEN;
        for (int k2 = 0; k2 < 64; k2++) {
            int sidx = k2*32 + lane;
            wout[base + sidx] = ws[r*2048 + sidx] * inv;
        }
    }
}

// ============================================================================
// HMMA attn@V: out = W @ V per z. CTA: 128 t x 64 dv, loop s chunks of 128.
// Weights split to bf16 hi/lo in-register; V pre-transposed [z][dv][s].
// grid (T/128, B*H), 256 threads.
// ============================================================================
#define AV_STR 136
#define AV_WPL (128*AV_STR)               // 17408 elems
#define AV_VPL (64*AV_STR)                // 8704 elems
#define AV_DSMEM ((2*AV_WPL + 2*AV_VPL)*2)  // 104448 bytes

__global__ __launch_bounds__(256)
void attn_v_mma(const float* __restrict__ wgt, const __nv_bfloat16* __restrict__ vth,
                const __nv_bfloat16* __restrict__ vtl, float* __restrict__ out)
{
    extern __shared__ __align__(16) __nv_bfloat16 smv[];
    const uint32_t sbase = s2u(smv);
    const uint32_t W_H = sbase;
    const uint32_t W_L = sbase + AV_WPL*2;
    const uint32_t V_H = sbase + 2*AV_WPL*2;
    const uint32_t V_L = V_H + AV_VPL*2;

    const int tid = threadIdx.x;
    const int lane = tid & 31, wid = tid >> 5;
    const int wm = wid & 3, wn = wid >> 2;
    const int z = blockIdx.y;
    const int b = z / HEADS, h = z % HEADS;
    const int t0 = blockIdx.x * 128;

    float acc[2][4][4];
    #pragma unroll
    for (int mf = 0; mf < 2; mf++)
        #pragma unroll
        for (int nf = 0; nf < 4; nf++)
            #pragma unroll
            for (int q = 0; q < 4; q++) acc[mf][nf][q] = 0.f;

    const int rowA = lane & 15;
    const int kA   = (lane >> 4) << 3;
    const int rowB = ((lane >> 4) << 3) + (lane & 7);
    const int kB   = ((lane >> 3) & 1) << 3;

    for (int s0 = 0; s0 < S_LEN; s0 += 128) {
        // V planes via cp.async: 64 rows x 128 cols bf16 (16 chunks/row)
        #pragma unroll
        for (int i = 0; i < 4; i++) {
            int u = tid + 256*i;          // 1024 chunks/plane
            int r = u >> 4, c = u & 15;
            cpa16(V_H + (uint32_t)((r*AV_STR + c*8)*2),
                  &vth[((size_t)z*64 + r)*2048 + s0 + c*8]);
            cpa16(V_L + (uint32_t)((r*AV_STR + c*8)*2),
                  &vtl[((size_t)z*64 + r)*2048 + s0 + c*8]);
        }
        asm volatile("cp.async.commit_group;" ::: "memory");

        // Weights fp32 -> hi/lo bf16 smem
        #pragma unroll
        for (int i = 0; i < 16; i++) {
            int u = tid + 256*i;          // 4096 float4 chunks
            int r = u >> 5, c4 = u & 31;
            float4 v = *(const float4*)&wgt[((size_t)z*T_LEN + t0 + r)*S_LEN + s0 + c4*4];
            __nv_bfloat16 h0 = __float2bfloat16(v.x), h1 = __float2bfloat16(v.y);
            __nv_bfloat16 h2 = __float2bfloat16(v.z), h3 = __float2bfloat16(v.w);
            uint32_t hA = (uint32_t)__bfloat16_as_ushort(h0) | ((uint32_t)__bfloat16_as_ushort(h1) << 16);
            uint32_t hB = (uint32_t)__bfloat16_as_ushort(h2) | ((uint32_t)__bfloat16_as_ushort(h3) << 16);
            uint32_t lA = pack_bf2(v.x - __bfloat162float(h0), v.y - __bfloat162float(h1));
            uint32_t lB = pack_bf2(v.z - __bfloat162float(h2), v.w - __bfloat162float(h3));
            uint32_t off = (uint32_t)((r*AV_STR + c4*4)*2);
            asm volatile("st.shared.v2.b32 [%0], {%1,%2};" :: "r"(W_H + off), "r"(hA), "r"(hB));
            asm volatile("st.shared.v2.b32 [%0], {%1,%2};" :: "r"(W_L + off), "r"(lA), "r"(lB));
        }
        asm volatile("cp.async.wait_group 0;" ::: "memory");
        __syncthreads();

        #pragma unroll
        for (int ks = 0; ks < 8; ks++) {
            const int k16 = ks * 16;
            uint32_t ah[2][4], al[2][4];
            #pragma unroll
            for (int mf = 0; mf < 2; mf++) {
                uint32_t off = (uint32_t)(((wm*32 + mf*16 + rowA)*AV_STR + k16 + kA) * 2);
                ldsm4(ah[mf], W_H + off);
                ldsm4(al[mf], W_L + off);
            }
            #pragma unroll
            for (int ng = 0; ng < 2; ng++) {
                uint32_t bh[4], bl[4];
                uint32_t off = (uint32_t)(((wn*32 + ng*16 + rowB)*AV_STR + k16 + kB) * 2);
                ldsm4(bh, V_H + off);
                ldsm4(bl, V_L + off);
                #pragma unroll
                for (int mf = 0; mf < 2; mf++) {
                    #pragma unroll
                    for (int nf2 = 0; nf2 < 2; nf2++) {
                        float* a4 = acc[mf][ng*2 + nf2];
                        mma_bf16(a4, ah[mf], bh[2*nf2], bh[2*nf2+1]);
                        mma_bf16(a4, al[mf], bh[2*nf2], bh[2*nf2+1]);
                        mma_bf16(a4, ah[mf], bl[2*nf2], bl[2*nf2+1]);
                    }
                }
            }
        }
        __syncthreads();
    }

    const int tq = lane >> 2, tr = lane & 3;
    #pragma unroll
    for (int mf = 0; mf < 2; mf++) {
        #pragma unroll
        for (int nf = 0; nf < 4; nf++) {
            const int row = t0 + wm*32 + mf*16 + tq;
            const int col = wn*32 + nf*8 + tr*2;
            float2 o0, o1;
            o0.x = acc[mf][nf][0]; o0.y = acc[mf][nf][1];
            o1.x = acc[mf][nf][2]; o1.y = acc[mf][nf][3];
            *(float2*)&out[((size_t)row*BATCH + b)*EMB + h*64 + col]       = o0;
            *(float2*)&out[((size_t)(row+8)*BATCH + b)*EMB + h*64 + col]   = o1;
        }
    }
}

// ============================================================================
extern "C" void kernel_launch(void* const* d_in, const int* in_sizes, int n_in,
                              void* d_out, int out_size)
{
    const float* query = (const float*)d_in[0];
    const float* key   = (const float*)d_in[1];
    const float* value = (const float*)d_in[2];
    const int*   mask  = (const int*)  d_in[3];
    const float* Wq = (const float*)d_in[4];  const float* bq = (const float*)d_in[5];
    const float* Wk = (const float*)d_in[6];  const float* bk = (const float*)d_in[7];
    const float* Wv = (const float*)d_in[8];  const float* bv = (const float*)d_in[9];
    const float* Wo = (const float*)d_in[10]; const float* bo = (const float*)d_in[11];
    float* out = (float*)d_out;

    float *gq, *gk, *gv, *ga, *gw;
    __nv_bfloat16 *ah, *al, *wh, *wl, *qh, *ql, *kh, *kl, *vth, *vtl;
    cudaGetSymbolAddress((void**)&gq, g_q);
    cudaGetSymbolAddress((void**)&gk, g_k);
    cudaGetSymbolAddress((void**)&gv, g_v);
    cudaGetSymbolAddress((void**)&ga, g_attn);
    cudaGetSymbolAddress((void**)&gw, g_w);
    cudaGetSymbolAddress((void**)&ah, g_ah);
    cudaGetSymbolAddress((void**)&al, g_al);
    cudaGetSymbolAddress((void**)&wh, g_wh);
    cudaGetSymbolAddress((void**)&wl, g_wl);
    cudaGetSymbolAddress((void**)&qh, g_qh);
    cudaGetSymbolAddress((void**)&ql, g_ql);
    cudaGetSymbolAddress((void**)&kh, g_kh);
    cudaGetSymbolAddress((void**)&kl, g_kl);
    cudaGetSymbolAddress((void**)&vth, g_vth);
    cudaGetSymbolAddress((void**)&vtl, g_vtl);

    const size_t attn_elems = (size_t)T_LEN*BATCH*EMB;
    const size_t w_elems    = (size_t)BATCH*HEADS*T_LEN*S_LEN;
    float* wptr = ((size_t)out_size >= attn_elems + w_elems) ? (out + attn_elems) : gw;

    cudaFuncSetAttribute(gemm_mma_bf16x3, cudaFuncAttributeMaxDynamicSharedMemorySize, GEMM_DSMEM);
    cudaFuncSetAttribute(attn_qk, cudaFuncAttributeMaxDynamicSharedMemorySize, QK_DSMEM);
    cudaFuncSetAttribute(attn_softmax2, cudaFuncAttributeMaxDynamicSharedMemorySize, SM2_DSMEM);
    cudaFuncSetAttribute(attn_v_mma, cudaFuncAttributeMaxDynamicSharedMemorySize, AV_DSMEM);

    const int act_n4 = (MROWS*EMB)/4;
    const int w_n4   = (EMB*EMB)/4;
    dim3 gemm_grid(GN/128, MROWS/128);

    // projections
    split_f32<<<1024, 256>>>(query, ah, al, act_n4);
    split_f32<<<512, 256>>>(Wq, wh, wl, w_n4);
    gemm_mma_bf16x3<<<gemm_grid, 256, GEMM_DSMEM>>>(ah, al, wh, wl, bq, gq, SCALING);

    split_f32<<<1024, 256>>>(key, ah, al, act_n4);
    split_f32<<<512, 256>>>(Wk, wh, wl, w_n4);
    gemm_mma_bf16x3<<<gemm_grid, 256, GEMM_DSMEM>>>(ah, al, wh, wl, bk, gk, 1.0f);

    split_f32<<<1024, 256>>>(value, ah, al, act_n4);
    split_f32<<<512, 256>>>(Wv, wh, wl, w_n4);
    gemm_mma_bf16x3<<<gemm_grid, 256, GEMM_DSMEM>>>(ah, al, wh, wl, bv, gv, 1.0f);

    // attention operand prep
    split_f32<<<1024, 256>>>(gq, qh, ql, act_n4);
    split_f32<<<1024, 256>>>(gk, kh, kl, act_n4);
    split_v_t<<<dim3(S_LEN/128, BATCH*HEADS), 256>>>(gv, vth, vtl);

    // scores -> softmax -> attn@V
    attn_qk<<<dim3(S_LEN/128, T_LEN/128, BATCH*HEADS), 256, QK_DSMEM>>>(qh, ql, kh, kl, wptr);
    attn_softmax2<<<dim3(T_LEN/16, BATCH*HEADS), 256, SM2_DSMEM>>>(wptr, mask);
    attn_v_mma<<<dim3(T_LEN/128, BATCH*HEADS), 256, AV_DSMEM>>>(wptr, vth, vtl, ga);

    // output projection
    split_f32<<<1024, 256>>>(ga, ah, al, act_n4);
    split_f32<<<512, 256>>>(Wo, wh, wl, w_n4);
    gemm_mma_bf16x3<<<gemm_grid, 256, GEMM_DSMEM>>>(ah, al, wh, wl, bo, out, 1.0f);
}